// round 1
// baseline (speedup 1.0000x reference)
#include <cuda_runtime.h>
#include <math.h>

// Problem constants
#define NB   256
#define NS   1024
#define NROWS (NB * NS)   // 262144

// Scratch (device globals: no allocations allowed)
__device__ float g_u[(size_t)NROWS * 128];   // 128 MB: u = gelu(LN(xW1+b1)) @ Wc1[5:,:] + bc1
__device__ float g_bx[(size_t)NROWS * 8];    // 8 MB (5 used, stride 8)

// ---------- packed fp32x2 helpers (FFMA2 path, 2x fp32 rate on sm_103a) ----------
__device__ __forceinline__ unsigned long long pack2(float a) {
    unsigned long long r; unsigned int ia = __float_as_uint(a);
    asm("mov.b64 %0, {%1,%2};" : "=l"(r) : "r"(ia), "r"(ia));
    return r;
}
__device__ __forceinline__ unsigned long long ffma2(unsigned long long a,
                                                    unsigned long long b,
                                                    unsigned long long c) {
    unsigned long long d;
    asm("fma.rn.f32x2 %0, %1, %2, %3;" : "=l"(d) : "l"(a), "l"(b), "l"(c));
    return d;
}
__device__ __forceinline__ float2 unpack2(unsigned long long v) {
    unsigned int lo, hi;
    asm("mov.b64 {%0,%1}, %2;" : "=r"(lo), "=r"(hi) : "l"(v));
    return make_float2(__uint_as_float(lo), __uint_as_float(hi));
}
__device__ __forceinline__ float gelu_exact(float x) {
    return 0.5f * x * (1.0f + erff(x * 0.7071067811865475f));
}
__device__ __forceinline__ float sigmoidf_(float v) { return 1.0f / (1.0f + expf(-v)); }

// ============================================================================
// Phase 1: per 64-row tile of (B*S):
//   h  = gelu(LN(x @ W1 + b1))          (h kept in SMEM only)
//   u  = h @ Wc1[5:133,:] + bc1  -> g_u
//   bx = h @ Winn + binn         -> g_bx
// 256 threads (16x16); each thread: 4 rows x 4 col-pairs, packed f32x2 FMAs.
// ============================================================================
__global__ __launch_bounds__(256, 2)
void p1_kernel(const float* __restrict__ x,   const float* __restrict__ W1,
               const float* __restrict__ b1,  const float* __restrict__ ln_g,
               const float* __restrict__ ln_b, const float* __restrict__ Winn,
               const float* __restrict__ binn, const float* __restrict__ Wc1,
               const float* __restrict__ bc1)
{
    __shared__ float  Hs[64 * 132];     // 33.8 KB  (h tile; also aliases Xs during stage 1)
    __shared__ float2 Wp[16 * 64];      // 8 KB weight tile as column pairs
    __shared__ float  sB1[128], sLG[128], sLB[128], sBC1[128], sWinn[128 * 5], sBinn[5];

    const int tid = threadIdx.x;
    const int tx  = tid & 15;           // col-pair group
    const int ty  = tid >> 4;           // row group
    const size_t row0 = (size_t)blockIdx.x * 64;

    if (tid < 128) {
        sB1[tid] = b1[tid];  sLG[tid] = ln_g[tid];
        sLB[tid] = ln_b[tid]; sBC1[tid] = bc1[tid];
    }
    if (tid < 5) sBinn[tid] = binn[tid];
    for (int i = tid; i < 640; i += 256) sWinn[i] = Winn[i];

    unsigned long long acc[4][4];
#pragma unroll
    for (int i = 0; i < 4; i++)
#pragma unroll
        for (int j = 0; j < 4; j++) acc[i][j] = 0ULL;

    float* Xs = Hs;  // Xs[16][65], only live during stage-1 k-loop

    // ---- stage 1: h = x @ W1 ----
    for (int k0 = 0; k0 < 128; k0 += 16) {
        __syncthreads();
        {   // x tile: 64 rows x 16 k, transposed into Xs[k][m]
            int r = tid >> 2, q = tid & 3;
            float4 v = *(const float4*)(x + (row0 + r) * 128 + k0 + q * 4);
            Xs[(q*4+0)*65 + r] = v.x;
            Xs[(q*4+1)*65 + r] = v.y;
            Xs[(q*4+2)*65 + r] = v.z;
            Xs[(q*4+3)*65 + r] = v.w;
        }
        {   // W1 tile: 16 k-rows x 128 cols as 64 pairs (conflict-free LDS.64 reads)
            int kk = tid >> 4, p0 = (tid & 15) * 4;
            const float* wr = W1 + (size_t)(k0 + kk) * 128 + p0 * 2;
            float4 v0 = *(const float4*)(wr);
            float4 v1 = *(const float4*)(wr + 4);
            Wp[kk*64 + p0 + 0] = make_float2(v0.x, v0.y);
            Wp[kk*64 + p0 + 1] = make_float2(v0.z, v0.w);
            Wp[kk*64 + p0 + 2] = make_float2(v1.x, v1.y);
            Wp[kk*64 + p0 + 3] = make_float2(v1.z, v1.w);
        }
        __syncthreads();
#pragma unroll
        for (int kk = 0; kk < 16; kk++) {
            unsigned long long ap[4], bp[4];
#pragma unroll
            for (int rr = 0; rr < 4; rr++) ap[rr] = pack2(Xs[kk*65 + ty*4 + rr]);
#pragma unroll
            for (int cc = 0; cc < 4; cc++)
                bp[cc] = *(const unsigned long long*)&Wp[kk*64 + cc*16 + tx];
#pragma unroll
            for (int rr = 0; rr < 4; rr++)
#pragma unroll
                for (int cc = 0; cc < 4; cc++)
                    acc[rr][cc] = ffma2(ap[rr], bp[cc], acc[rr][cc]);
        }
    }
    __syncthreads();

    // h = acc + b1 -> Hs
#pragma unroll
    for (int rr = 0; rr < 4; rr++) {
        int r = ty*4 + rr;
#pragma unroll
        for (int cc = 0; cc < 4; cc++) {
            int c = (cc*16 + tx) * 2;
            float2 hv = unpack2(acc[rr][cc]);
            *(float2*)&Hs[r*132 + c] = make_float2(hv.x + sB1[c], hv.y + sB1[c+1]);
        }
    }
    __syncthreads();

    // ---- LayerNorm + exact GELU (one warp-row at a time, 8 rows/warp) ----
    {
        int warp = tid >> 5, lane = tid & 31;
        for (int r = warp; r < 64; r += 8) {
            float4 v = *(const float4*)&Hs[r*132 + lane*4];
            float s = v.x + v.y + v.z + v.w;
#pragma unroll
            for (int off = 16; off; off >>= 1) s += __shfl_xor_sync(0xffffffffu, s, off);
            float mu = s * 0.0078125f;
            float dx = v.x - mu, dy = v.y - mu, dz = v.z - mu, dw = v.w - mu;
            float q = dx*dx + dy*dy + dz*dz + dw*dw;
#pragma unroll
            for (int off = 16; off; off >>= 1) q += __shfl_xor_sync(0xffffffffu, q, off);
            float rs = rsqrtf(q * 0.0078125f + 1e-5f);
            int c = lane * 4;
            float h0 = dx*rs*sLG[c+0] + sLB[c+0];
            float h1 = dy*rs*sLG[c+1] + sLB[c+1];
            float h2 = dz*rs*sLG[c+2] + sLB[c+2];
            float h3 = dw*rs*sLG[c+3] + sLB[c+3];
            *(float4*)&Hs[r*132 + c] =
                make_float4(gelu_exact(h0), gelu_exact(h1), gelu_exact(h2), gelu_exact(h3));
        }
    }
    __syncthreads();

    // ---- bx = h @ Winn + binn (320 small dots) ----
    for (int idx = tid; idx < 64 * 5; idx += 256) {
        int r = idx / 5, c = idx - r * 5;
        float a = sBinn[c];
#pragma unroll 4
        for (int k = 0; k < 128; k++) a += Hs[r*132 + k] * sWinn[k*5 + c];
        g_bx[(row0 + r) * 8 + c] = a;
    }

    // ---- stage 2: u = h @ Wc1[5:,:] + bc1 ----
#pragma unroll
    for (int i = 0; i < 4; i++)
#pragma unroll
        for (int j = 0; j < 4; j++) acc[i][j] = 0ULL;

    for (int k0 = 0; k0 < 128; k0 += 16) {
        __syncthreads();
        {
            int kk = tid >> 4, p0 = (tid & 15) * 4;
            const float* wr = Wc1 + (size_t)(5 + k0 + kk) * 128 + p0 * 2;
            float4 v0 = *(const float4*)(wr);
            float4 v1 = *(const float4*)(wr + 4);
            Wp[kk*64 + p0 + 0] = make_float2(v0.x, v0.y);
            Wp[kk*64 + p0 + 1] = make_float2(v0.z, v0.w);
            Wp[kk*64 + p0 + 2] = make_float2(v1.x, v1.y);
            Wp[kk*64 + p0 + 3] = make_float2(v1.z, v1.w);
        }
        __syncthreads();
#pragma unroll
        for (int kk = 0; kk < 16; kk++) {
            unsigned long long ap[4], bp[4];
#pragma unroll
            for (int rr = 0; rr < 4; rr++) ap[rr] = pack2(Hs[(ty*4+rr)*132 + k0 + kk]);
#pragma unroll
            for (int cc = 0; cc < 4; cc++)
                bp[cc] = *(const unsigned long long*)&Wp[kk*64 + cc*16 + tx];
#pragma unroll
            for (int rr = 0; rr < 4; rr++)
#pragma unroll
                for (int cc = 0; cc < 4; cc++)
                    acc[rr][cc] = ffma2(ap[rr], bp[cc], acc[rr][cc]);
        }
    }
    // u -> global
#pragma unroll
    for (int rr = 0; rr < 4; rr++) {
        size_t r = row0 + ty*4 + rr;
#pragma unroll
        for (int cc = 0; cc < 4; cc++) {
            int c = (cc*16 + tx) * 2;
            float2 uv = unpack2(acc[rr][cc]);
            *(float2*)&g_u[r*128 + c] = make_float2(uv.x + sBC1[c], uv.y + sBC1[c+1]);
        }
    }
}

// ============================================================================
// Phase 2: sequential scan, one warp per batch (256 warps -> single wave).
// State s[5] replicated in every lane; per step:
//   s_lin = A(s)+bx_t;  m = gelu(s_lin@Wc1_s + u_t);  s = s_lin + cs*tanh(m@Wc2+bc2)
// m@Wc2 reduced with 5-level shfl.bfly (all-reduce -> no broadcast needed).
// u_t / bx_t prefetched one step ahead.
// ============================================================================
__global__ __launch_bounds__(128)
void p2_kernel(const float* __restrict__ Wc1, const float* __restrict__ Wc2,
               const float* __restrict__ bc2, const float* __restrict__ corr_scale,
               const float* __restrict__ raw_aL, const float* __restrict__ raw_aT,
               const float* __restrict__ raw_g,  const float* __restrict__ raw_aR,
               const float* __restrict__ omega,  float* __restrict__ out)
{
    const int warp = threadIdx.x >> 5, lane = threadIdx.x & 31;
    const int b = blockIdx.x * 4 + warp;

    const float aL = sigmoidf_(raw_aL[0]) * 0.15f + 0.85f;
    const float aT = sigmoidf_(raw_aT[0]) * 0.25f + 0.70f;
    const float gg = sigmoidf_(raw_g[0])  * 0.20f + 0.80f;
    const float aR = sigmoidf_(raw_aR[0]) * 0.40f;
    const float om = omega[0];
    const float gc = gg * cosf(om), gs = gg * sinf(om);
    const float cs = corr_scale[0];

    const int c0 = lane * 4;
    float Ws[5][4], Wo[4][5], bb[5];
#pragma unroll
    for (int i = 0; i < 5; i++)
#pragma unroll
        for (int c = 0; c < 4; c++) Ws[i][c] = Wc1[i*128 + c0 + c];
#pragma unroll
    for (int c = 0; c < 4; c++)
#pragma unroll
        for (int k = 0; k < 5; k++) Wo[c][k] = Wc2[(c0 + c)*5 + k];
#pragma unroll
    for (int k = 0; k < 5; k++) bb[k] = bc2[k];

    float s0 = 0.f, s1 = 0.f, s2 = 0.f, s3 = 0.f, s4 = 0.f;
    const float4* up  = (const float4*)(g_u + (size_t)b * 1024 * 128);
    const float*  bxp = g_bx + (size_t)b * 1024 * 8;

    float4 u = up[lane];
    float x0 = bxp[0], x1 = bxp[1], x2 = bxp[2], x3 = bxp[3], x4 = bxp[4];

    for (int t = 0; t < 1024; t++) {
        // prefetch t+1
        float4 un = u; float n0 = x0, n1 = x1, n2 = x2, n3 = x3, n4 = x4;
        if (t < 1023) {
            un = up[(t + 1) * 32 + lane];
            const float* bn = bxp + (t + 1) * 8;
            n0 = bn[0]; n1 = bn[1]; n2 = bn[2]; n3 = bn[3]; n4 = bn[4];
        }

        float l0 = s0*aL + x0;
        float l1 = s1*aT + x1;
        float l2 = s2*gc + s3*gs + x2;
        float l3 = s3*gc - s2*gs + x3;
        float l4 = s4*aR + x4;

        float m0 = gelu_exact(u.x + l0*Ws[0][0] + l1*Ws[1][0] + l2*Ws[2][0] + l3*Ws[3][0] + l4*Ws[4][0]);
        float m1 = gelu_exact(u.y + l0*Ws[0][1] + l1*Ws[1][1] + l2*Ws[2][1] + l3*Ws[3][1] + l4*Ws[4][1]);
        float m2 = gelu_exact(u.z + l0*Ws[0][2] + l1*Ws[1][2] + l2*Ws[2][2] + l3*Ws[3][2] + l4*Ws[4][2]);
        float m3 = gelu_exact(u.w + l0*Ws[0][3] + l1*Ws[1][3] + l2*Ws[2][3] + l3*Ws[3][3] + l4*Ws[4][3]);

        float p0 = m0*Wo[0][0] + m1*Wo[1][0] + m2*Wo[2][0] + m3*Wo[3][0];
        float p1 = m0*Wo[0][1] + m1*Wo[1][1] + m2*Wo[2][1] + m3*Wo[3][1];
        float p2 = m0*Wo[0][2] + m1*Wo[1][2] + m2*Wo[2][2] + m3*Wo[3][2];
        float p3 = m0*Wo[0][3] + m1*Wo[1][3] + m2*Wo[2][3] + m3*Wo[3][3];
        float p4 = m0*Wo[0][4] + m1*Wo[1][4] + m2*Wo[2][4] + m3*Wo[3][4];
#pragma unroll
        for (int off = 16; off; off >>= 1) {
            p0 += __shfl_xor_sync(0xffffffffu, p0, off);
            p1 += __shfl_xor_sync(0xffffffffu, p1, off);
            p2 += __shfl_xor_sync(0xffffffffu, p2, off);
            p3 += __shfl_xor_sync(0xffffffffu, p3, off);
            p4 += __shfl_xor_sync(0xffffffffu, p4, off);
        }
        s0 = l0 + cs * tanhf(p0 + bb[0]);
        s1 = l1 + cs * tanhf(p1 + bb[1]);
        s2 = l2 + cs * tanhf(p2 + bb[2]);
        s3 = l3 + cs * tanhf(p3 + bb[3]);
        s4 = l4 + cs * tanhf(p4 + bb[4]);

        u = un; x0 = n0; x1 = n1; x2 = n2; x3 = n3; x4 = n4;
    }

    if (lane == 0) {
        out[b*5+0] = s0; out[b*5+1] = s1; out[b*5+2] = s2;
        out[b*5+3] = s3; out[b*5+4] = s4;
    }
}

// ============================================================================
extern "C" void kernel_launch(void* const* d_in, const int* in_sizes, int n_in,
                              void* d_out, int out_size)
{
    (void)in_sizes; (void)n_in; (void)out_size;
    const float* x    = (const float*)d_in[0];
    const float* W1   = (const float*)d_in[1];
    const float* b1   = (const float*)d_in[2];
    const float* ln_g = (const float*)d_in[3];
    const float* ln_b = (const float*)d_in[4];
    const float* Winn = (const float*)d_in[5];
    const float* binn = (const float*)d_in[6];
    const float* Wc1  = (const float*)d_in[7];
    const float* bc1  = (const float*)d_in[8];
    const float* Wc2  = (const float*)d_in[9];
    const float* bc2  = (const float*)d_in[10];
    const float* cscl = (const float*)d_in[11];
    const float* raL  = (const float*)d_in[12];
    const float* raT  = (const float*)d_in[13];
    const float* rg   = (const float*)d_in[14];
    const float* raR  = (const float*)d_in[15];
    const float* om   = (const float*)d_in[16];

    p1_kernel<<<NROWS / 64, 256>>>(x, W1, b1, ln_g, ln_b, Winn, binn, Wc1, bc1);
    p2_kernel<<<NB / 4, 128>>>(Wc1, Wc2, bc2, cscl, raL, raT, rg, raR, om, (float*)d_out);
}